// round 4
// baseline (speedup 1.0000x reference)
#include <cuda_runtime.h>
#include <math.h>

#define TT 2048
#define DM 1024
#define NH 16
#define HDI 64
#define BB 2
#define MT (BB*TT)   // 4096
#define SQ 68        // padded smem row stride (floats) for 64-wide rows

// Scratch (allocation-free: __device__ globals)
__device__ float g_Q[BB*NH*TT*HDI];   // [B,H,T,Hd]
__device__ float g_K[BB*NH*TT*HDI];
__device__ float g_V[BB*NH*TT*HDI];
__device__ float g_O[MT*DM];          // attention output in [B,T,D]

// ---------------------------------------------------------------------------
// NT GEMM: C[M,N] = A[M,K] @ W[N,K]^T (+bias), M=4096, N=K=1024.
// which = 0/1/2 : write to g_Q/g_K/g_V in [B,H,T,Hd] layout (fused reshape)
// which = 3     : A = g_O, out = x + alpha*(C + bias)  (fused residual)
// 128x128 tile, BK=8, 256 threads, 8x8 micro-tile, register prefetch.
// ---------------------------------------------------------------------------
__global__ __launch_bounds__(256, 2) void proj_gemm(
    const float* __restrict__ Aext, const float* __restrict__ W,
    const float* __restrict__ bias, int which,
    const float* __restrict__ xres, const float* __restrict__ alphap,
    float* __restrict__ outf)
{
    __shared__ float As[8*132];   // [k][m], padded stride 132
    __shared__ float Ws[8*132];   // [k][n]

    const float* A = (which == 3) ? g_O : Aext;

    const int tid = threadIdx.x;
    const int tx = tid & 15, ty = tid >> 4;
    const int bm = blockIdx.y * 128;
    const int bn = blockIdx.x * 128;
    const int lrow = tid >> 1;          // 0..127
    const int lk   = (tid & 1) * 4;     // 0 or 4

    const float* Ap = A + (bm + lrow) * DM + lk;
    const float* Wp = W + (bn + lrow) * DM + lk;

    float acc[8][8];
    #pragma unroll
    for (int i = 0; i < 8; i++)
        #pragma unroll
        for (int j = 0; j < 8; j++) acc[i][j] = 0.f;

    float4 av = *(const float4*)(Ap);
    float4 wv = *(const float4*)(Wp);

    for (int k0 = 0; k0 < DM; k0 += 8) {
        As[(lk+0)*132 + lrow] = av.x;
        As[(lk+1)*132 + lrow] = av.y;
        As[(lk+2)*132 + lrow] = av.z;
        As[(lk+3)*132 + lrow] = av.w;
        Ws[(lk+0)*132 + lrow] = wv.x;
        Ws[(lk+1)*132 + lrow] = wv.y;
        Ws[(lk+2)*132 + lrow] = wv.z;
        Ws[(lk+3)*132 + lrow] = wv.w;
        __syncthreads();
        if (k0 + 8 < DM) {                 // prefetch next tile (hides LDG latency)
            av = *(const float4*)(Ap + k0 + 8);
            wv = *(const float4*)(Wp + k0 + 8);
        }
        #pragma unroll
        for (int kk = 0; kk < 8; kk++) {
            float4 a0 = *(float4*)&As[kk*132 + ty*8];
            float4 a1 = *(float4*)&As[kk*132 + ty*8 + 4];
            float4 b0 = *(float4*)&Ws[kk*132 + tx*8];
            float4 b1 = *(float4*)&Ws[kk*132 + tx*8 + 4];
            float a[8] = {a0.x,a0.y,a0.z,a0.w,a1.x,a1.y,a1.z,a1.w};
            float b[8] = {b0.x,b0.y,b0.z,b0.w,b1.x,b1.y,b1.z,b1.w};
            #pragma unroll
            for (int i = 0; i < 8; i++)
                #pragma unroll
                for (int j = 0; j < 8; j++)
                    acc[i][j] += a[i] * b[j];
        }
        __syncthreads();
    }

    if (which < 3) {
        float* outp = (which == 0) ? g_Q : (which == 1) ? g_K : g_V;
        #pragma unroll
        for (int i = 0; i < 8; i++) {
            int m = bm + ty*8 + i;
            int b_ = m >> 11, t_ = m & 2047;
            #pragma unroll
            for (int jv = 0; jv < 8; jv += 4) {
                int n0 = bn + tx*8 + jv;            // tx*8..+7 stays inside one head
                float4 bv4 = *(const float4*)&bias[n0];
                int h = n0 >> 6, hd = n0 & 63;
                float4 o;
                o.x = acc[i][jv+0] + bv4.x;
                o.y = acc[i][jv+1] + bv4.y;
                o.z = acc[i][jv+2] + bv4.z;
                o.w = acc[i][jv+3] + bv4.w;
                *(float4*)&outp[((b_*NH + h)*TT + t_)*HDI + hd] = o;
            }
        }
    } else {
        float alpha = *alphap;
        #pragma unroll
        for (int i = 0; i < 8; i++) {
            int m = bm + ty*8 + i;
            #pragma unroll
            for (int jv = 0; jv < 8; jv += 4) {
                int n0 = bn + tx*8 + jv;
                float4 bv4 = *(const float4*)&bias[n0];
                float4 xv  = *(const float4*)&xres[m*DM + n0];
                float4 o;
                o.x = xv.x + alpha * (acc[i][jv+0] + bv4.x);
                o.y = xv.y + alpha * (acc[i][jv+1] + bv4.y);
                o.z = xv.z + alpha * (acc[i][jv+2] + bv4.z);
                o.w = xv.w + alpha * (acc[i][jv+3] + bv4.w);
                *(float4*)&outf[m*DM + n0] = o;
            }
        }
    }
}

// ---------------------------------------------------------------------------
// Streaming sigmoid attention. One block = (b*H+h, q-tile of 128).
// Single pass: accumulate numerator (gates@V) and denominator (row sums) —
// sigmoid gating needs no running-max rescale.
// smem: Qs[128][68] Ks[64][68] Vs[64][68] Ss[128][68] denom[128] = 104960 B
// ---------------------------------------------------------------------------
__global__ __launch_bounds__(256, 2) void attn_kernel()
{
    extern __shared__ float smn[];
    float* Qs = smn;                  // 128*SQ
    float* Ks = Qs + 128*SQ;          // 64*SQ
    float* Vs = Ks + 64*SQ;           // 64*SQ
    float* Ss = Vs + 64*SQ;           // 128*SQ
    float* denomS = Ss + 128*SQ;      // 128

    const int bh = blockIdx.x;        // 0..31
    const int qt = blockIdx.y;        // 0..15
    const int tid = threadIdx.x;
    const int tx = tid & 15, ty = tid >> 4;

    const float* Qb = g_Q + (bh*TT + qt*128) * HDI;
    const float* Kb = g_K + bh*TT*HDI;
    const float* Vb = g_V + bh*TT*HDI;

    // load Q tile (128 x 64)
    for (int i = tid; i < 128*16; i += 256) {
        int r = i >> 4, c = (i & 15) * 4;
        *(float4*)&Qs[r*SQ + c] = *(const float4*)(Qb + r*HDI + c);
    }

    float accO[8][4];
    #pragma unroll
    for (int i = 0; i < 8; i++)
        #pragma unroll
        for (int j = 0; j < 4; j++) accO[i][j] = 0.f;
    float dreg = 0.f;   // denominator accumulator (threads tid<128: row=tid)

    for (int s0 = 0; s0 < TT; s0 += 64) {
        __syncthreads();   // previous tile fully consumed (also fences Q load)
        // load K,V tiles (64 x 64 each)
        for (int i = tid; i < 64*16; i += 256) {
            int r = i >> 4, c = (i & 15) * 4;
            *(float4*)&Ks[r*SQ + c] = *(const float4*)(Kb + (s0+r)*HDI + c);
            *(float4*)&Vs[r*SQ + c] = *(const float4*)(Vb + (s0+r)*HDI + c);
        }
        __syncthreads();

        // S[128][64] = Q @ K^T  (8x4 per thread)
        float sc[8][4];
        #pragma unroll
        for (int i = 0; i < 8; i++)
            #pragma unroll
            for (int j = 0; j < 4; j++) sc[i][j] = 0.f;

        #pragma unroll 2
        for (int d = 0; d < 64; d += 4) {
            float4 b4[4];
            #pragma unroll
            for (int j = 0; j < 4; j++)
                b4[j] = *(float4*)&Ks[(tx*4+j)*SQ + d];
            #pragma unroll
            for (int i = 0; i < 8; i++) {
                float4 a = *(float4*)&Qs[(ty*8+i)*SQ + d];
                #pragma unroll
                for (int j = 0; j < 4; j++)
                    sc[i][j] += a.x*b4[j].x + a.y*b4[j].y + a.z*b4[j].z + a.w*b4[j].w;
            }
        }
        // sigmoid gate -> Ss
        #pragma unroll
        for (int i = 0; i < 8; i++) {
            float4 g;
            g.x = 1.f / (1.f + __expf(-0.125f * sc[i][0]));
            g.y = 1.f / (1.f + __expf(-0.125f * sc[i][1]));
            g.z = 1.f / (1.f + __expf(-0.125f * sc[i][2]));
            g.w = 1.f / (1.f + __expf(-0.125f * sc[i][3]));
            *(float4*)&Ss[(ty*8+i)*SQ + tx*4] = g;
        }
        __syncthreads();

        // denominator: row sums of Ss (one row per thread, tid<128)
        if (tid < 128) {
            float s = 0.f;
            #pragma unroll
            for (int c = 0; c < 64; c += 4) {
                float4 v = *(float4*)&Ss[tid*SQ + c];
                s += (v.x + v.y) + (v.z + v.w);
            }
            dreg += s;
        }

        // O[128][64] += Ss @ Vs  (8x4 per thread)
        #pragma unroll 2
        for (int s = 0; s < 64; s += 4) {
            float4 v0 = *(float4*)&Vs[(s+0)*SQ + tx*4];
            float4 v1 = *(float4*)&Vs[(s+1)*SQ + tx*4];
            float4 v2 = *(float4*)&Vs[(s+2)*SQ + tx*4];
            float4 v3 = *(float4*)&Vs[(s+3)*SQ + tx*4];
            #pragma unroll
            for (int i = 0; i < 8; i++) {
                float4 a = *(float4*)&Ss[(ty*8+i)*SQ + s];
                accO[i][0] += a.x*v0.x + a.y*v1.x + a.z*v2.x + a.w*v3.x;
                accO[i][1] += a.x*v0.y + a.y*v1.y + a.z*v2.y + a.w*v3.y;
                accO[i][2] += a.x*v0.z + a.y*v1.z + a.z*v2.z + a.w*v3.z;
                accO[i][3] += a.x*v0.w + a.y*v1.w + a.z*v2.w + a.w*v3.w;
            }
        }
    }

    if (tid < 128) denomS[tid] = dreg + 1e-6f;
    __syncthreads();

    const int b_ = bh >> 4, h = bh & 15;
    #pragma unroll
    for (int i = 0; i < 8; i++) {
        int m = ty*8 + i;
        float inv = 1.0f / denomS[m];
        int t_ = qt*128 + m;
        float4 o;
        o.x = accO[i][0] * inv;
        o.y = accO[i][1] * inv;
        o.z = accO[i][2] * inv;
        o.w = accO[i][3] * inv;
        *(float4*)&g_O[(b_*TT + t_)*DM + h*HDI + tx*4] = o;
    }
}

// ---------------------------------------------------------------------------
extern "C" void kernel_launch(void* const* d_in, const int* in_sizes, int n_in,
                              void* d_out, int out_size)
{
    const float* x  = (const float*)d_in[0];
    const float* wq = (const float*)d_in[1];
    const float* bq = (const float*)d_in[2];
    const float* wk = (const float*)d_in[3];
    const float* bk = (const float*)d_in[4];
    const float* wv = (const float*)d_in[5];
    const float* bv = (const float*)d_in[6];
    const float* wo = (const float*)d_in[7];
    const float* bo = (const float*)d_in[8];
    const float* al = (const float*)d_in[9];
    float* out = (float*)d_out;

    cudaFuncSetAttribute(attn_kernel,
                         cudaFuncAttributeMaxDynamicSharedMemorySize, 104960);

    dim3 gg(DM/128, MT/128);          // (8, 32)
    proj_gemm<<<gg, 256>>>(x, wq, bq, 0, nullptr, nullptr, nullptr);
    proj_gemm<<<gg, 256>>>(x, wk, bk, 1, nullptr, nullptr, nullptr);
    proj_gemm<<<gg, 256>>>(x, wv, bv, 2, nullptr, nullptr, nullptr);

    dim3 ga(BB*NH, TT/128);           // (32, 16)
    attn_kernel<<<ga, 256, 104960>>>();

    proj_gemm<<<gg, 256>>>(nullptr, wo, bo, 3, x, al, out);
}

// round 5
// speedup vs baseline: 1.8619x; 1.8619x over previous
#include <cuda_runtime.h>
#include <cuda_bf16.h>
#include <math.h>

#define TT 2048
#define DM 1024
#define NH 16
#define HDI 64
#define BB 2
#define MT (BB*TT)     // 4096
#define K3 3072        // split-K: [hi | lo/hi | hi/lo]
#define GS 40          // proj smem stride (bf16): 80B/row -> conflict-free ldmatrix
#define QS 200         // attn Q/K smem stride (bf16): 400B/row -> conflict-free
#define VS 72          // attn V smem stride

typedef __nv_bfloat16 bf16;
typedef __nv_bfloat162 bf162;

// ---------------- scratch (__device__ globals; no allocation) ----------------
__device__ bf16 g_X3[MT*K3];              // x split:   [hi | lo | hi]
__device__ bf16 g_W3[4][DM*K3];           // weights:   [hi | hi | lo]  (q,k,v,o)
__device__ bf16 g_Q3[BB*NH*TT*192];       // per-head Q split [qh|ql|qh]
__device__ bf16 g_K3[BB*NH*TT*192];       // per-head K split [kh|kh|kl]
__device__ bf16 g_Vb[BB*NH*TT*HDI];       // V direct bf16
__device__ bf16 g_O3[MT*K3];              // attn out split [oh|ol|oh] (A-format for out-proj)

// ---------------- helpers ----------------
__device__ __forceinline__ unsigned pack2(float a, float b) {
    bf162 t = __floats2bfloat162_rn(a, b);   // .x = a (low), .y = b
    return *reinterpret_cast<unsigned*>(&t);
}
__device__ __forceinline__ void st2(bf16* p, bf16 a, bf16 b) {
    bf162 t; t.x = a; t.y = b;
    *reinterpret_cast<bf162*>(p) = t;
}
__device__ __forceinline__ void mma16816(float* c,
    unsigned a0, unsigned a1, unsigned a2, unsigned a3, unsigned b0, unsigned b1) {
    asm volatile(
        "mma.sync.aligned.m16n8k16.row.col.f32.bf16.bf16.f32 "
        "{%0,%1,%2,%3},{%4,%5,%6,%7},{%8,%9},{%0,%1,%2,%3};\n"
        : "+f"(c[0]), "+f"(c[1]), "+f"(c[2]), "+f"(c[3])
        : "r"(a0), "r"(a1), "r"(a2), "r"(a3), "r"(b0), "r"(b1));
}
__device__ __forceinline__ void ldsm4(unsigned& r0, unsigned& r1, unsigned& r2, unsigned& r3, unsigned addr) {
    asm volatile("ldmatrix.sync.aligned.m8n8.x4.shared.b16 {%0,%1,%2,%3},[%4];\n"
        : "=r"(r0), "=r"(r1), "=r"(r2), "=r"(r3) : "r"(addr));
}
__device__ __forceinline__ void ldsm4t(unsigned& r0, unsigned& r1, unsigned& r2, unsigned& r3, unsigned addr) {
    asm volatile("ldmatrix.sync.aligned.m8n8.x4.trans.shared.b16 {%0,%1,%2,%3},[%4];\n"
        : "=r"(r0), "=r"(r1), "=r"(r2), "=r"(r3) : "r"(addr));
}

// ---------------- split conversion: fp32 -> [hi|lo|hi] (A) or [hi|hi|lo] (W) ----------------
__global__ void split_cvt(const float* __restrict__ src, int which)
{
    int idx = blockIdx.x * 256 + threadIdx.x;
    int r = idx >> 10, k = idx & 1023;
    float a = src[idx];
    bf16 h = __float2bfloat16_rn(a);
    bf16 l = __float2bfloat16_rn(a - __bfloat162float(h));
    bf16* d = (which == 0) ? (g_X3 + (size_t)r * K3) : (g_W3[which - 1] + (size_t)r * K3);
    d[k] = h;
    if (which == 0) { d[1024 + k] = l; d[2048 + k] = h; }
    else            { d[1024 + k] = h; d[2048 + k] = l; }
}

// ---------------- projection GEMM (bf16 tensor cores, split-K=3072) ----------------
// C[M=4096,N=1024] = A'[M,3072] . W'[N,3072]^T (+bias)
// mode 0/1/2: write Q3/K3/Vb per-head layouts; mode 3: A'=g_O3, out = x + alpha*(C+bias)
__global__ __launch_bounds__(256, 2) void proj_mma(
    const float* __restrict__ bias, int mode,
    const float* __restrict__ xres, const float* __restrict__ alphap,
    float* __restrict__ outf)
{
    __shared__ bf16 As[2][128 * GS];
    __shared__ bf16 Bs[2][128 * GS];

    const bf16* A = (mode == 3) ? g_O3 : g_X3;
    const bf16* W = g_W3[(mode == 3) ? 3 : mode];

    const int tid  = threadIdx.x;
    const int lane = tid & 31, wid = tid >> 5;
    const int wm = wid >> 2, wn = wid & 3;       // 2 m-warps x 4 n-warps; warp tile 64x32
    const int bm = blockIdx.y * 128, bn = blockIdx.x * 128;

    const int lr = tid >> 1;                     // smem row 0..127
    const int lc = (tid & 1) * 16;               // col 0 / 16
    const bf16* Ap = A + (size_t)(bm + lr) * K3 + lc;
    const bf16* Wp = W + (size_t)(bn + lr) * K3 + lc;

    float c[4][4][4];
    #pragma unroll
    for (int i = 0; i < 4; i++)
        #pragma unroll
        for (int j = 0; j < 4; j++)
            #pragma unroll
            for (int q = 0; q < 4; q++) c[i][j][q] = 0.f;

    unsigned sA = (unsigned)__cvta_generic_to_shared(&As[0][0]);
    unsigned sB = (unsigned)__cvta_generic_to_shared(&Bs[0][0]);
    const unsigned bufB = 128 * GS * 2;          // byte offset between buffers

    // ldmatrix per-lane address components
    const int a_row  = lane & 15;
    const int a_coff = (lane >> 4) << 3;
    const int b_row  = (lane & 7) + ((lane >> 4) << 3);
    const int b_coff = lane & 8;

    // preload tile 0
    {
        uint4 a0v = *(const uint4*)(Ap);
        uint4 a1v = *(const uint4*)(Ap + 8);
        uint4 b0v = *(const uint4*)(Wp);
        uint4 b1v = *(const uint4*)(Wp + 8);
        *(uint4*)&As[0][lr * GS + lc]     = a0v;
        *(uint4*)&As[0][lr * GS + lc + 8] = a1v;
        *(uint4*)&Bs[0][lr * GS + lc]     = b0v;
        *(uint4*)&Bs[0][lr * GS + lc + 8] = b1v;
    }

    int buf = 0;
    for (int k0 = 0; k0 < K3; k0 += 32) {
        __syncthreads();
        uint4 a0v, a1v, b0v, b1v;
        const bool more = (k0 + 32 < K3);
        if (more) {
            a0v = *(const uint4*)(Ap + k0 + 32);
            a1v = *(const uint4*)(Ap + k0 + 40);
            b0v = *(const uint4*)(Wp + k0 + 32);
            b1v = *(const uint4*)(Wp + k0 + 40);
        }
        unsigned cA = sA + (unsigned)buf * bufB;
        unsigned cB = sB + (unsigned)buf * bufB;
        #pragma unroll
        for (int d = 0; d < 32; d += 16) {
            unsigned af[4][4];
            #pragma unroll
            for (int mi = 0; mi < 4; mi++)
                ldsm4(af[mi][0], af[mi][1], af[mi][2], af[mi][3],
                      cA + (unsigned)(((wm * 64 + mi * 16 + a_row) * GS + d + a_coff) * 2));
            #pragma unroll
            for (int np = 0; np < 2; np++) {
                unsigned b0, b1, b2, b3;
                ldsm4(b0, b1, b2, b3,
                      cB + (unsigned)(((wn * 32 + np * 16 + b_row) * GS + d + b_coff) * 2));
                #pragma unroll
                for (int mi = 0; mi < 4; mi++) {
                    mma16816(c[mi][np * 2],     af[mi][0], af[mi][1], af[mi][2], af[mi][3], b0, b1);
                    mma16816(c[mi][np * 2 + 1], af[mi][0], af[mi][1], af[mi][2], af[mi][3], b2, b3);
                }
            }
        }
        if (more) {
            int nb = buf ^ 1;
            *(uint4*)&As[nb][lr * GS + lc]     = a0v;
            *(uint4*)&As[nb][lr * GS + lc + 8] = a1v;
            *(uint4*)&Bs[nb][lr * GS + lc]     = b0v;
            *(uint4*)&Bs[nb][lr * GS + lc + 8] = b1v;
        }
        buf ^= 1;
    }

    // epilogue
    const int g  = lane >> 2;
    const int q2 = (lane & 3) * 2;
    if (mode == 3) {
        const float alpha = *alphap;
        #pragma unroll
        for (int mi = 0; mi < 4; mi++)
            #pragma unroll
            for (int half = 0; half < 2; half++) {
                int m = bm + wm * 64 + mi * 16 + g + half * 8;
                #pragma unroll
                for (int ni = 0; ni < 4; ni++) {
                    int n = bn + wn * 32 + ni * 8 + q2;
                    float2 o;
                    o.x = xres[(size_t)m * DM + n]     + alpha * (c[mi][ni][half * 2 + 0] + bias[n]);
                    o.y = xres[(size_t)m * DM + n + 1] + alpha * (c[mi][ni][half * 2 + 1] + bias[n + 1]);
                    *(float2*)&outf[(size_t)m * DM + n] = o;
                }
            }
    } else {
        #pragma unroll
        for (int mi = 0; mi < 4; mi++)
            #pragma unroll
            for (int half = 0; half < 2; half++) {
                int m = bm + wm * 64 + mi * 16 + g + half * 8;
                int b_ = m >> 11, t_ = m & 2047;
                #pragma unroll
                for (int ni = 0; ni < 4; ni++) {
                    int n = bn + wn * 32 + ni * 8 + q2;
                    int h = n >> 6, hd = n & 63;
                    size_t rb = ((size_t)(b_ * NH + h) * TT + t_);
                    float v0 = c[mi][ni][half * 2 + 0] + bias[n];
                    float v1 = c[mi][ni][half * 2 + 1] + bias[n + 1];
                    if (mode == 2) {
                        st2(&g_Vb[rb * 64 + hd], __float2bfloat16_rn(v0), __float2bfloat16_rn(v1));
                    } else {
                        bf16 h0 = __float2bfloat16_rn(v0), h1 = __float2bfloat16_rn(v1);
                        bf16 l0 = __float2bfloat16_rn(v0 - __bfloat162float(h0));
                        bf16 l1 = __float2bfloat16_rn(v1 - __bfloat162float(h1));
                        bf16* dst = (mode == 0) ? g_Q3 : g_K3;
                        size_t rr = rb * 192;
                        st2(dst + rr + hd, h0, h1);
                        if (mode == 0) { st2(dst + rr + 64 + hd, l0, l1); st2(dst + rr + 128 + hd, h0, h1); }
                        else           { st2(dst + rr + 64 + hd, h0, h1); st2(dst + rr + 128 + hd, l0, l1); }
                    }
                }
            }
    }
}

// ---------------- attention (tensor cores): S=Q3.K3^T (K=192 split), sigmoid, O=P.V ----------------
// CTA = (b*H+h, 128-q tile); 8 warps, warp = 16 q-rows x full 128-key tile.
__global__ __launch_bounds__(256, 1) void attn_mma()
{
    extern __shared__ bf16 sm[];
    bf16* Qs = sm;                 // 128 x QS
    bf16* Ks = Qs + 128 * QS;      // 128 x QS
    bf16* Vs = Ks + 128 * QS;      // 128 x VS

    const int tid = threadIdx.x, lane = tid & 31, wid = tid >> 5;
    const int bh = blockIdx.x, qt = blockIdx.y;
    const bf16* Qg = g_Q3 + (size_t)(bh * TT + qt * 128) * 192;
    const bf16* Kg = g_K3 + (size_t)bh * TT * 192;
    const bf16* Vg = g_Vb + (size_t)bh * TT * 64;

    // load Q tile (128 x 192)
    for (int i = tid; i < 128 * 24; i += 256) {
        int r = i / 24, cg = i % 24;
        *(uint4*)&Qs[r * QS + cg * 8] = *(const uint4*)(Qg + r * 192 + cg * 8);
    }

    float oc[8][4];
    #pragma unroll
    for (int i = 0; i < 8; i++)
        #pragma unroll
        for (int j = 0; j < 4; j++) oc[i][j] = 0.f;
    float ds0 = 0.f, ds1 = 0.f;

    unsigned sQ = (unsigned)__cvta_generic_to_shared(Qs);
    unsigned sK = (unsigned)__cvta_generic_to_shared(Ks);
    unsigned sV = (unsigned)__cvta_generic_to_shared(Vs);
    const int a_row  = lane & 15;
    const int a_coff = (lane >> 4) << 3;
    const int b_row  = (lane & 7) + ((lane >> 4) << 3);
    const int b_coff = lane & 8;
    const int v_row  = (lane & 7) + (lane & 8);
    const int v_coff = (lane >> 4) << 3;
    const int qr = wid * 16;

    for (int kt = 0; kt < 16; kt++) {
        __syncthreads();
        const bf16* Kt = Kg + (size_t)kt * 128 * 192;
        for (int i = tid; i < 128 * 24; i += 256) {
            int r = i / 24, cg = i % 24;
            *(uint4*)&Ks[r * QS + cg * 8] = *(const uint4*)(Kt + r * 192 + cg * 8);
        }
        const bf16* Vt = Vg + (size_t)kt * 128 * 64;
        for (int i = tid; i < 128 * 8; i += 256) {
            int r = i >> 3, cg = i & 7;
            *(uint4*)&Vs[r * VS + cg * 8] = *(const uint4*)(Vt + r * 64 + cg * 8);
        }
        __syncthreads();

        // S = Q . K^T : warp 16 x 128, K-dim 192 (12 k16 steps)
        float sc[16][4];
        #pragma unroll
        for (int i = 0; i < 16; i++)
            #pragma unroll
            for (int j = 0; j < 4; j++) sc[i][j] = 0.f;

        #pragma unroll
        for (int d16 = 0; d16 < 12; d16++) {
            unsigned a0, a1, a2, a3;
            ldsm4(a0, a1, a2, a3, sQ + (unsigned)(((qr + a_row) * QS + d16 * 16 + a_coff) * 2));
            #pragma unroll
            for (int np = 0; np < 8; np++) {
                unsigned b0, b1, b2, b3;
                ldsm4(b0, b1, b2, b3, sK + (unsigned)(((np * 16 + b_row) * QS + d16 * 16 + b_coff) * 2));
                mma16816(sc[np * 2],     a0, a1, a2, a3, b0, b1);
                mma16816(sc[np * 2 + 1], a0, a1, a2, a3, b2, b3);
            }
        }

        // sigmoid gates (scores/8) + denominator partials
        #pragma unroll
        for (int nt = 0; nt < 16; nt++) {
            float g0 = 1.f / (1.f + __expf(-0.125f * sc[nt][0]));
            float g1 = 1.f / (1.f + __expf(-0.125f * sc[nt][1]));
            float g2 = 1.f / (1.f + __expf(-0.125f * sc[nt][2]));
            float g3 = 1.f / (1.f + __expf(-0.125f * sc[nt][3]));
            sc[nt][0] = g0; sc[nt][1] = g1; sc[nt][2] = g2; sc[nt][3] = g3;
            ds0 += g0 + g1;   // row g
            ds1 += g2 + g3;   // row g+8
        }

        // O += P . V : in-register C->A fragment conversion, V via ldmatrix.trans
        #pragma unroll
        for (int t = 0; t < 8; t++) {
            unsigned a0 = pack2(sc[2 * t][0],     sc[2 * t][1]);
            unsigned a1 = pack2(sc[2 * t][2],     sc[2 * t][3]);
            unsigned a2 = pack2(sc[2 * t + 1][0], sc[2 * t + 1][1]);
            unsigned a3 = pack2(sc[2 * t + 1][2], sc[2 * t + 1][3]);
            #pragma unroll
            for (int nq = 0; nq < 4; nq++) {
                unsigned b0, b1, b2, b3;
                ldsm4t(b0, b1, b2, b3, sV + (unsigned)(((t * 16 + v_row) * VS + nq * 16 + v_coff) * 2));
                mma16816(oc[nq * 2],     a0, a1, a2, a3, b0, b1);
                mma16816(oc[nq * 2 + 1], a0, a1, a2, a3, b2, b3);
            }
        }
    }

    // denominator reduce across the quad (lanes sharing a row)
    ds0 += __shfl_xor_sync(0xffffffffu, ds0, 1);
    ds0 += __shfl_xor_sync(0xffffffffu, ds0, 2);
    ds1 += __shfl_xor_sync(0xffffffffu, ds1, 1);
    ds1 += __shfl_xor_sync(0xffffffffu, ds1, 2);
    const float inv0 = 1.f / (ds0 + 1e-6f);
    const float inv1 = 1.f / (ds1 + 1e-6f);

    // epilogue: normalized O -> g_O3 in [oh|ol|oh] split layout
    const int b_ = bh >> 4, h = bh & 15;
    const int g = lane >> 2, q2 = (lane & 3) * 2;
    const int t0 = qt * 128 + qr + g;
    const size_t r0 = (size_t)(b_ * TT + t0) * K3 + h * 64;
    const size_t r1 = r0 + (size_t)8 * K3;
    #pragma unroll
    for (int nt = 0; nt < 8; nt++) {
        int hd = nt * 8 + q2;
        float v0 = oc[nt][0] * inv0, v1 = oc[nt][1] * inv0;
        float v2 = oc[nt][2] * inv1, v3 = oc[nt][3] * inv1;
        {
            bf16 h0 = __float2bfloat16_rn(v0), h1 = __float2bfloat16_rn(v1);
            bf16 l0 = __float2bfloat16_rn(v0 - __bfloat162float(h0));
            bf16 l1 = __float2bfloat16_rn(v1 - __bfloat162float(h1));
            st2(&g_O3[r0 + hd], h0, h1);
            st2(&g_O3[r0 + 1024 + hd], l0, l1);
            st2(&g_O3[r0 + 2048 + hd], h0, h1);
        }
        {
            bf16 h0 = __float2bfloat16_rn(v2), h1 = __float2bfloat16_rn(v3);
            bf16 l0 = __float2bfloat16_rn(v2 - __bfloat162float(h0));
            bf16 l1 = __float2bfloat16_rn(v3 - __bfloat162float(h1));
            st2(&g_O3[r1 + hd], h0, h1);
            st2(&g_O3[r1 + 1024 + hd], l0, l1);
            st2(&g_O3[r1 + 2048 + hd], h0, h1);
        }
    }
}

// ---------------------------------------------------------------------------
extern "C" void kernel_launch(void* const* d_in, const int* in_sizes, int n_in,
                              void* d_out, int out_size)
{
    const float* x  = (const float*)d_in[0];
    const float* wq = (const float*)d_in[1];
    const float* bq = (const float*)d_in[2];
    const float* wk = (const float*)d_in[3];
    const float* bk = (const float*)d_in[4];
    const float* wv = (const float*)d_in[5];
    const float* bv = (const float*)d_in[6];
    const float* wo = (const float*)d_in[7];
    const float* bo = (const float*)d_in[8];
    const float* al = (const float*)d_in[9];
    float* out = (float*)d_out;

    static int smem_set = 0;
    cudaFuncSetAttribute(attn_mma, cudaFuncAttributeMaxDynamicSharedMemorySize, 120832);
    (void)smem_set;

    // split conversions
    split_cvt<<<MT * DM / 256, 256>>>(x, 0);
    split_cvt<<<DM * DM / 256, 256>>>(wq, 1);
    split_cvt<<<DM * DM / 256, 256>>>(wk, 2);
    split_cvt<<<DM * DM / 256, 256>>>(wv, 3);
    split_cvt<<<DM * DM / 256, 256>>>(wo, 4);

    dim3 gg(DM / 128, MT / 128);      // (8, 32)
    proj_mma<<<gg, 256>>>(bq, 0, nullptr, nullptr, nullptr);
    proj_mma<<<gg, 256>>>(bk, 1, nullptr, nullptr, nullptr);
    proj_mma<<<gg, 256>>>(bv, 2, nullptr, nullptr, nullptr);

    dim3 ga(BB * NH, TT / 128);       // (32, 16)
    attn_mma<<<ga, 256, 120832>>>();

    proj_mma<<<gg, 256>>>(bo, 3, x, al, out);
}

// round 8
// speedup vs baseline: 4.5140x; 2.4244x over previous
#include <cuda_runtime.h>
#include <cuda_bf16.h>
#include <math.h>

#define TT 2048
#define DM 1024
#define NH 16
#define HDI 64
#define BB 2
#define MT (BB*TT)     // 4096
#define GS 40          // proj smem stride (bf16): 80B/row -> conflict-free ldmatrix
#define QS 72          // attn smem stride (bf16): 144B/row -> conflict-free ldmatrix

typedef __nv_bfloat16 bf16;
typedef __nv_bfloat162 bf162;

// ---------------- scratch (__device__ globals; no allocation) ----------------
__device__ bf16 g_Xb[MT*DM];              // x in bf16
__device__ bf16 g_Wb[4][DM*DM];           // weights bf16 (q,k,v,o)
__device__ bf16 g_Qb[BB*NH*TT*HDI];       // per-head [B,H,T,64]
__device__ bf16 g_Kb[BB*NH*TT*HDI];
__device__ bf16 g_Vb[BB*NH*TT*HDI];
__device__ bf16 g_Ob[MT*DM];              // attn out [B,T,D] bf16 (A of out-proj)

// ---------------- helpers ----------------
__device__ __forceinline__ unsigned pack2(float a, float b) {
    bf162 t = __floats2bfloat162_rn(a, b);
    return *reinterpret_cast<unsigned*>(&t);
}
__device__ __forceinline__ void st2(bf16* p, bf16 a, bf16 b) {
    bf162 t; t.x = a; t.y = b;
    *reinterpret_cast<bf162*>(p) = t;
}
__device__ __forceinline__ void mma16816(float* c,
    unsigned a0, unsigned a1, unsigned a2, unsigned a3, unsigned b0, unsigned b1) {
    asm volatile(
        "mma.sync.aligned.m16n8k16.row.col.f32.bf16.bf16.f32 "
        "{%0,%1,%2,%3},{%4,%5,%6,%7},{%8,%9},{%0,%1,%2,%3};\n"
        : "+f"(c[0]), "+f"(c[1]), "+f"(c[2]), "+f"(c[3])
        : "r"(a0), "r"(a1), "r"(a2), "r"(a3), "r"(b0), "r"(b1));
}
__device__ __forceinline__ void ldsm4(unsigned& r0, unsigned& r1, unsigned& r2, unsigned& r3, unsigned addr) {
    asm volatile("ldmatrix.sync.aligned.m8n8.x4.shared.b16 {%0,%1,%2,%3},[%4];\n"
        : "=r"(r0), "=r"(r1), "=r"(r2), "=r"(r3) : "r"(addr));
}
__device__ __forceinline__ void ldsm4t(unsigned& r0, unsigned& r1, unsigned& r2, unsigned& r3, unsigned addr) {
    asm volatile("ldmatrix.sync.aligned.m8n8.x4.trans.shared.b16 {%0,%1,%2,%3},[%4];\n"
        : "=r"(r0), "=r"(r1), "=r"(r2), "=r"(r3) : "r"(addr));
}

// ---------------- fp32 -> bf16 conversion (dst selected IN DEVICE CODE) ----------------
// which: 0 -> g_Xb, 1..4 -> g_Wb[0..3]
__global__ void cvt_bf16(const float* __restrict__ src, int which)
{
    size_t i = ((size_t)blockIdx.x * 256 + threadIdx.x) * 4;
    bf16* dst = (which == 0) ? g_Xb : g_Wb[which - 1];
    float4 v = *(const float4*)(src + i);
    bf162 a = __floats2bfloat162_rn(v.x, v.y);
    bf162 b = __floats2bfloat162_rn(v.z, v.w);
    *(bf162*)(dst + i)     = a;
    *(bf162*)(dst + i + 2) = b;
}

// ---------------- projection GEMM (bf16 tensor cores, K=1024) ----------------
// C[M=4096,N=1024] = A[M,1024] . W[N,1024]^T (+bias)
// mode 0/1/2: write g_Qb/g_Kb/g_Vb per-head bf16; mode 3: A=g_Ob, out = x + alpha*(C+bias)
__global__ __launch_bounds__(256, 2) void proj_mma(
    const float* __restrict__ bias, int mode,
    const float* __restrict__ xres, const float* __restrict__ alphap,
    float* __restrict__ outf)
{
    __shared__ bf16 As[2][128 * GS];
    __shared__ bf16 Bs[2][128 * GS];

    const bf16* A = (mode == 3) ? g_Ob : g_Xb;
    const bf16* W = g_Wb[(mode == 3) ? 3 : mode];

    const int tid  = threadIdx.x;
    const int lane = tid & 31, wid = tid >> 5;
    const int wm = wid >> 2, wn = wid & 3;       // 2 m-warps x 4 n-warps; warp tile 64x32
    const int bm = blockIdx.y * 128, bn = blockIdx.x * 128;

    const int lr = tid >> 1;                     // smem row 0..127
    const int lc = (tid & 1) * 16;               // col 0 / 16
    const bf16* Ap = A + (size_t)(bm + lr) * DM + lc;
    const bf16* Wp = W + (size_t)(bn + lr) * DM + lc;

    float c[4][4][4];
    #pragma unroll
    for (int i = 0; i < 4; i++)
        #pragma unroll
        for (int j = 0; j < 4; j++)
            #pragma unroll
            for (int q = 0; q < 4; q++) c[i][j][q] = 0.f;

    unsigned sA = (unsigned)__cvta_generic_to_shared(&As[0][0]);
    unsigned sB = (unsigned)__cvta_generic_to_shared(&Bs[0][0]);
    const unsigned bufB = 128 * GS * 2;

    const int a_row  = lane & 15;
    const int a_coff = (lane >> 4) << 3;
    const int b_row  = (lane & 7) + ((lane >> 4) << 3);
    const int b_coff = lane & 8;

    // preload tile 0
    {
        uint4 a0v = *(const uint4*)(Ap);
        uint4 a1v = *(const uint4*)(Ap + 8);
        uint4 b0v = *(const uint4*)(Wp);
        uint4 b1v = *(const uint4*)(Wp + 8);
        *(uint4*)&As[0][lr * GS + lc]     = a0v;
        *(uint4*)&As[0][lr * GS + lc + 8] = a1v;
        *(uint4*)&Bs[0][lr * GS + lc]     = b0v;
        *(uint4*)&Bs[0][lr * GS + lc + 8] = b1v;
    }

    int buf = 0;
    for (int k0 = 0; k0 < DM; k0 += 32) {
        __syncthreads();
        uint4 a0v, a1v, b0v, b1v;
        const bool more = (k0 + 32 < DM);
        if (more) {
            a0v = *(const uint4*)(Ap + k0 + 32);
            a1v = *(const uint4*)(Ap + k0 + 40);
            b0v = *(const uint4*)(Wp + k0 + 32);
            b1v = *(const uint4*)(Wp + k0 + 40);
        }
        unsigned cA = sA + (unsigned)buf * bufB;
        unsigned cB = sB + (unsigned)buf * bufB;
        #pragma unroll
        for (int d = 0; d < 32; d += 16) {
            unsigned af[4][4];
            #pragma unroll
            for (int mi = 0; mi < 4; mi++)
                ldsm4(af[mi][0], af[mi][1], af[mi][2], af[mi][3],
                      cA + (unsigned)(((wm * 64 + mi * 16 + a_row) * GS + d + a_coff) * 2));
            #pragma unroll
            for (int np = 0; np < 2; np++) {
                unsigned b0, b1, b2, b3;
                ldsm4(b0, b1, b2, b3,
                      cB + (unsigned)(((wn * 32 + np * 16 + b_row) * GS + d + b_coff) * 2));
                #pragma unroll
                for (int mi = 0; mi < 4; mi++) {
                    mma16816(c[mi][np * 2],     af[mi][0], af[mi][1], af[mi][2], af[mi][3], b0, b1);
                    mma16816(c[mi][np * 2 + 1], af[mi][0], af[mi][1], af[mi][2], af[mi][3], b2, b3);
                }
            }
        }
        if (more) {
            int nb = buf ^ 1;
            *(uint4*)&As[nb][lr * GS + lc]     = a0v;
            *(uint4*)&As[nb][lr * GS + lc + 8] = a1v;
            *(uint4*)&Bs[nb][lr * GS + lc]     = b0v;
            *(uint4*)&Bs[nb][lr * GS + lc + 8] = b1v;
        }
        buf ^= 1;
    }

    // epilogue
    const int g  = lane >> 2;
    const int q2 = (lane & 3) * 2;
    if (mode == 3) {
        const float alpha = *alphap;
        #pragma unroll
        for (int mi = 0; mi < 4; mi++)
            #pragma unroll
            for (int half = 0; half < 2; half++) {
                int m = bm + wm * 64 + mi * 16 + g + half * 8;
                #pragma unroll
                for (int ni = 0; ni < 4; ni++) {
                    int n = bn + wn * 32 + ni * 8 + q2;
                    float2 o;
                    o.x = xres[(size_t)m * DM + n]     + alpha * (c[mi][ni][half * 2 + 0] + bias[n]);
                    o.y = xres[(size_t)m * DM + n + 1] + alpha * (c[mi][ni][half * 2 + 1] + bias[n + 1]);
                    *(float2*)&outf[(size_t)m * DM + n] = o;
                }
            }
    } else {
        bf16* outp = (mode == 0) ? g_Qb : (mode == 1) ? g_Kb : g_Vb;
        #pragma unroll
        for (int mi = 0; mi < 4; mi++)
            #pragma unroll
            for (int half = 0; half < 2; half++) {
                int m = bm + wm * 64 + mi * 16 + g + half * 8;
                int b_ = m >> 11, t_ = m & 2047;
                #pragma unroll
                for (int ni = 0; ni < 4; ni++) {
                    int n = bn + wn * 32 + ni * 8 + q2;
                    int h = n >> 6, hd = n & 63;
                    size_t rb = ((size_t)(b_ * NH + h) * TT + t_);
                    float v0 = c[mi][ni][half * 2 + 0] + bias[n];
                    float v1 = c[mi][ni][half * 2 + 1] + bias[n + 1];
                    st2(&outp[rb * 64 + hd],
                        __float2bfloat16_rn(v0), __float2bfloat16_rn(v1));
                }
            }
    }
}

// ---------------- attention (tensor cores): S=Q.K^T (K=64), sigmoid, O=P.V ----------------
// CTA = (b*H+h, 128-q tile); 8 warps, warp = 16 q-rows x full 128-key tile.
__global__ __launch_bounds__(256, 2) void attn_mma()
{
    extern __shared__ bf16 sm[];
    bf16* Qs = sm;                 // 128 x QS
    bf16* Ks = Qs + 128 * QS;      // 128 x QS
    bf16* Vs = Ks + 128 * QS;      // 128 x QS

    const int tid = threadIdx.x, lane = tid & 31, wid = tid >> 5;
    const int bh = blockIdx.x, qt = blockIdx.y;
    const bf16* Qg = g_Qb + (size_t)(bh * TT + qt * 128) * 64;
    const bf16* Kg = g_Kb + (size_t)bh * TT * 64;
    const bf16* Vg = g_Vb + (size_t)bh * TT * 64;

    // load Q tile (128 x 64)
    for (int i = tid; i < 128 * 8; i += 256) {
        int r = i >> 3, cg = i & 7;
        *(uint4*)&Qs[r * QS + cg * 8] = *(const uint4*)(Qg + r * 64 + cg * 8);
    }

    float oc[8][4];
    #pragma unroll
    for (int i = 0; i < 8; i++)
        #pragma unroll
        for (int j = 0; j < 4; j++) oc[i][j] = 0.f;
    float ds0 = 0.f, ds1 = 0.f;

    unsigned sQ = (unsigned)__cvta_generic_to_shared(Qs);
    unsigned sK = (unsigned)__cvta_generic_to_shared(Ks);
    unsigned sV = (unsigned)__cvta_generic_to_shared(Vs);
    const int a_row  = lane & 15;
    const int a_coff = (lane >> 4) << 3;
    const int b_row  = (lane & 7) + ((lane >> 4) << 3);
    const int b_coff = lane & 8;
    const int v_row  = (lane & 7) + (lane & 8);
    const int v_coff = (lane >> 4) << 3;
    const int qr = wid * 16;

    for (int kt = 0; kt < 16; kt++) {
        __syncthreads();
        const bf16* Kt = Kg + (size_t)kt * 128 * 64;
        const bf16* Vt = Vg + (size_t)kt * 128 * 64;
        for (int i = tid; i < 128 * 8; i += 256) {
            int r = i >> 3, cg = i & 7;
            *(uint4*)&Ks[r * QS + cg * 8] = *(const uint4*)(Kt + r * 64 + cg * 8);
            *(uint4*)&Vs[r * QS + cg * 8] = *(const uint4*)(Vt + r * 64 + cg * 8);
        }
        __syncthreads();

        // S = Q . K^T : warp 16 x 128, K-dim 64 (4 k16 steps)
        float sc[16][4];
        #pragma unroll
        for (int i = 0; i < 16; i++)
            #pragma unroll
            for (int j = 0; j < 4; j++) sc[i][j] = 0.f;

        #pragma unroll
        for (int d16 = 0; d16 < 4; d16++) {
            unsigned a0, a1, a2, a3;
            ldsm4(a0, a1, a2, a3, sQ + (unsigned)(((qr + a_row) * QS + d16 * 16 + a_coff) * 2));
            #pragma unroll
            for (int np = 0; np < 8; np++) {
                unsigned b0, b1, b2, b3;
                ldsm4(b0, b1, b2, b3, sK + (unsigned)(((np * 16 + b_row) * QS + d16 * 16 + b_coff) * 2));
                mma16816(sc[np * 2],     a0, a1, a2, a3, b0, b1);
                mma16816(sc[np * 2 + 1], a0, a1, a2, a3, b2, b3);
            }
        }

        // sigmoid gates (scores/8) + denominator partials
        #pragma unroll
        for (int nt = 0; nt < 16; nt++) {
            float g0 = 1.f / (1.f + __expf(-0.125f * sc[nt][0]));
            float g1 = 1.f / (1.f + __expf(-0.125f * sc[nt][1]));
            float g2 = 1.f / (1.f + __expf(-0.125f * sc[nt][2]));
            float g3 = 1.f / (1.f + __expf(-0.125f * sc[nt][3]));
            sc[nt][0] = g0; sc[nt][1] = g1; sc[nt][2] = g2; sc[nt][3] = g3;
            ds0 += g0 + g1;   // row g
            ds1 += g2 + g3;   // row g+8
        }

        // O += P . V : in-register C->A fragment conversion, V via ldmatrix.trans
        #pragma unroll
        for (int t = 0; t < 8; t++) {
            unsigned a0 = pack2(sc[2 * t][0],     sc[2 * t][1]);
            unsigned a1 = pack2(sc[2 * t][2],     sc[2 * t][3]);
            unsigned a2 = pack2(sc[2 * t + 1][0], sc[2 * t + 1][1]);
            unsigned a3 = pack2(sc[2 * t + 1][2], sc[2 * t + 1][3]);
            #pragma unroll
            for (int nq = 0; nq < 4; nq++) {
                unsigned b0, b1, b2, b3;
                ldsm4t(b0, b1, b2, b3, sV + (unsigned)(((t * 16 + v_row) * QS + nq * 16 + v_coff) * 2));
                mma16816(oc[nq * 2],     a0, a1, a2, a3, b0, b1);
                mma16816(oc[nq * 2 + 1], a0, a1, a2, a3, b2, b3);
            }
        }
    }

    // denominator reduce across the quad (lanes sharing a row)
    ds0 += __shfl_xor_sync(0xffffffffu, ds0, 1);
    ds0 += __shfl_xor_sync(0xffffffffu, ds0, 2);
    ds1 += __shfl_xor_sync(0xffffffffu, ds1, 1);
    ds1 += __shfl_xor_sync(0xffffffffu, ds1, 2);
    const float inv0 = 1.f / (ds0 + 1e-6f);
    const float inv1 = 1.f / (ds1 + 1e-6f);

    // epilogue: normalized O -> g_Ob [B,T,D] bf16
    const int b_ = bh >> 4, h = bh & 15;
    const int g = lane >> 2, q2 = (lane & 3) * 2;
    const int t0 = qt * 128 + qr + g;
    const size_t r0 = (size_t)(b_ * TT + t0) * DM + h * 64;
    const size_t r1 = r0 + (size_t)8 * DM;
    #pragma unroll
    for (int nt = 0; nt < 8; nt++) {
        int hd = nt * 8 + q2;
        st2(&g_Ob[r0 + hd], __float2bfloat16_rn(oc[nt][0] * inv0),
                            __float2bfloat16_rn(oc[nt][1] * inv0));
        st2(&g_Ob[r1 + hd], __float2bfloat16_rn(oc[nt][2] * inv1),
                            __float2bfloat16_rn(oc[nt][3] * inv1));
    }
}

// ---------------------------------------------------------------------------
extern "C" void kernel_launch(void* const* d_in, const int* in_sizes, int n_in,
                              void* d_out, int out_size)
{
    const float* x  = (const float*)d_in[0];
    const float* wq = (const float*)d_in[1];
    const float* bq = (const float*)d_in[2];
    const float* wk = (const float*)d_in[3];
    const float* bk = (const float*)d_in[4];
    const float* wv = (const float*)d_in[5];
    const float* bv = (const float*)d_in[6];
    const float* wo = (const float*)d_in[7];
    const float* bo = (const float*)d_in[8];
    const float* al = (const float*)d_in[9];
    float* out = (float*)d_out;

    cudaFuncSetAttribute(attn_mma, cudaFuncAttributeMaxDynamicSharedMemorySize, 55296);

    // bf16 conversions (destinations selected inside the kernel — never pass
    // __device__ symbols from host code)
    cvt_bf16<<<MT * DM / 1024, 256>>>(x, 0);
    cvt_bf16<<<DM * DM / 1024, 256>>>(wq, 1);
    cvt_bf16<<<DM * DM / 1024, 256>>>(wk, 2);
    cvt_bf16<<<DM * DM / 1024, 256>>>(wv, 3);
    cvt_bf16<<<DM * DM / 1024, 256>>>(wo, 4);

    dim3 gg(DM / 128, MT / 128);      // (8, 32)
    proj_mma<<<gg, 256>>>(bq, 0, nullptr, nullptr, nullptr);
    proj_mma<<<gg, 256>>>(bk, 1, nullptr, nullptr, nullptr);
    proj_mma<<<gg, 256>>>(bv, 2, nullptr, nullptr, nullptr);

    dim3 ga(BB * NH, TT / 128);       // (32, 16)
    attn_mma<<<ga, 256, 55296>>>();

    proj_mma<<<gg, 256>>>(bo, 3, x, al, out);
}

// round 10
// speedup vs baseline: 7.8659x; 1.7426x over previous
#include <cuda_runtime.h>
#include <cuda_bf16.h>
#include <math.h>

#define TT 2048
#define DM 1024
#define NH 16
#define HDI 64
#define BB 2
#define MT (BB*TT)     // 4096
#define GS 40          // proj smem stride (bf16): 80B/row -> conflict-free ldmatrix
#define QS 72          // attn smem stride (bf16): 144B/row -> conflict-free ldmatrix

// proj pipeline: 3 stages, each A(10240B)+B(10240B)
#define PSTG 20480
#define PSMEM (3*PSTG)
// attn pipeline: 2 stages, each K(18432B)+V(18432B); Q staged in stage1 K region
#define ASTG 36864
#define ASMEM (2*ASTG)

typedef __nv_bfloat16 bf16;
typedef __nv_bfloat162 bf162;

// ---------------- scratch (__device__ globals; no allocation) ----------------
__device__ bf16 g_Xb[MT*DM];              // x in bf16
__device__ bf16 g_Wb[4][DM*DM];           // weights bf16 (q,k,v,o)
__device__ bf16 g_Qb[BB*NH*TT*HDI];       // per-head [B,H,T,64]
__device__ bf16 g_Kb[BB*NH*TT*HDI];
__device__ bf16 g_Vb[BB*NH*TT*HDI];
__device__ bf16 g_Ob[MT*DM];              // attn out [B,T,D] bf16 (A of out-proj)

// ---------------- helpers ----------------
__device__ __forceinline__ unsigned pack2(float a, float b) {
    bf162 t = __floats2bfloat162_rn(a, b);
    return *reinterpret_cast<unsigned*>(&t);
}
__device__ __forceinline__ void st2(bf16* p, bf16 a, bf16 b) {
    bf162 t; t.x = a; t.y = b;
    *reinterpret_cast<bf162*>(p) = t;
}
__device__ __forceinline__ void mma16816(float* c,
    unsigned a0, unsigned a1, unsigned a2, unsigned a3, unsigned b0, unsigned b1) {
    asm volatile(
        "mma.sync.aligned.m16n8k16.row.col.f32.bf16.bf16.f32 "
        "{%0,%1,%2,%3},{%4,%5,%6,%7},{%8,%9},{%0,%1,%2,%3};\n"
        : "+f"(c[0]), "+f"(c[1]), "+f"(c[2]), "+f"(c[3])
        : "r"(a0), "r"(a1), "r"(a2), "r"(a3), "r"(b0), "r"(b1));
}
__device__ __forceinline__ void ldsm4(unsigned& r0, unsigned& r1, unsigned& r2, unsigned& r3, unsigned addr) {
    asm volatile("ldmatrix.sync.aligned.m8n8.x4.shared.b16 {%0,%1,%2,%3},[%4];\n"
        : "=r"(r0), "=r"(r1), "=r"(r2), "=r"(r3) : "r"(addr));
}
__device__ __forceinline__ void ldsm4t(unsigned& r0, unsigned& r1, unsigned& r2, unsigned& r3, unsigned addr) {
    asm volatile("ldmatrix.sync.aligned.m8n8.x4.trans.shared.b16 {%0,%1,%2,%3},[%4];\n"
        : "=r"(r0), "=r"(r1), "=r"(r2), "=r"(r3) : "r"(addr));
}
__device__ __forceinline__ void cpa16(unsigned dst, const void* src) {
    asm volatile("cp.async.cg.shared.global [%0], [%1], 16;" :: "r"(dst), "l"(src));
}
#define CP_COMMIT() asm volatile("cp.async.commit_group;")
#define CP_WAIT1()  asm volatile("cp.async.wait_group 1;")
#define CP_WAIT0()  asm volatile("cp.async.wait_group 0;")

// sigmoid(s/8) = 0.5*tanh(s/16)+0.5  (single MUFU via tanh.approx)
__device__ __forceinline__ float sigm8(float s) {
    float t;
    asm("tanh.approx.f32 %0, %1;" : "=f"(t) : "f"(s * 0.0625f));
    return fmaf(t, 0.5f, 0.5f);
}

// ---------------- fp32 -> bf16, all 5 tensors in one launch ----------------
// blocks 0..4095: x (4M elems); 4096..8191: wq/wk/wv/wo (1M each)
__global__ void cvt_all(const float* __restrict__ x,
                        const float* __restrict__ wq, const float* __restrict__ wk,
                        const float* __restrict__ wv, const float* __restrict__ wo)
{
    int b = blockIdx.x;
    const float* src;
    bf16* dst;
    size_t off;
    if (b < 4096) { src = x; dst = g_Xb; off = (size_t)b * 1024; }
    else {
        int w = (b - 4096) >> 10, r = (b - 4096) & 1023;
        src = (w == 0) ? wq : (w == 1) ? wk : (w == 2) ? wv : wo;
        dst = g_Wb[w];
        off = 0;
        src += (size_t)r * 1024;
        dst += (size_t)w * 0 + (size_t)r * 1024;   // row within weight
    }
    size_t i = off + (size_t)threadIdx.x * 4;
    float4 v = *(const float4*)(src + (b < 4096 ? i : (size_t)threadIdx.x * 4));
    bf16* d = dst + (b < 4096 ? i : (size_t)threadIdx.x * 4);
    *(bf162*)(d)     = __floats2bfloat162_rn(v.x, v.y);
    *(bf162*)(d + 2) = __floats2bfloat162_rn(v.z, v.w);
}

// ---------------- projection GEMM (HMMA, cp.async 3-stage) ----------------
// C[M=4096,N=1024] = A[M,1024] . W[N,1024]^T (+bias)
// grid.z + base_mode -> mode. 0/1/2: per-head Q/K/V; 3: out = x + alpha*(C+bias)
__global__ __launch_bounds__(256, 2) void proj_mma(
    const float* __restrict__ b0p, const float* __restrict__ b1p,
    const float* __restrict__ b2p, int base_mode,
    const float* __restrict__ xres, const float* __restrict__ alphap,
    float* __restrict__ outf)
{
    extern __shared__ char smraw[];
    const int tid  = threadIdx.x;
    const int lane = tid & 31, wid = tid >> 5;
    const int wm = wid >> 2, wn = wid & 3;       // 2 m-warps x 4 n-warps; warp 64x32
    const int mode = base_mode + blockIdx.z;
    const float* bias = (blockIdx.z == 0) ? b0p : (blockIdx.z == 1) ? b1p : b2p;
    const int bm = blockIdx.y * 128, bn = blockIdx.x * 128;

    const bf16* A = (mode == 3) ? g_Ob : g_Xb;
    const bf16* W = g_Wb[mode];
    const bf16* Ag = A + (size_t)bm * DM;
    const bf16* Wg = W + (size_t)bn * DM;

    unsigned sb = (unsigned)__cvta_generic_to_shared(smraw);

    const int lrow = tid >> 2;        // 0..63? no: chunks: e=tid+i*256; row=e>>2
    (void)lrow;

    // issue stage loads for k-chunk kt into stage s (A+B, 512 chunks each matrix)
    auto issue = [&](int kt, int s) {
        const unsigned dA = sb + (unsigned)s * PSTG;
        const unsigned dB = dA + 10240;
        const int koff = kt * 32;
        #pragma unroll
        for (int i = 0; i < 2; i++) {
            int e = tid + i * 256;
            int row = e >> 2, c16 = e & 3;
            cpa16(dA + row * 80 + c16 * 16, Ag + (size_t)row * DM + koff + c16 * 8);
            cpa16(dB + row * 80 + c16 * 16, Wg + (size_t)row * DM + koff + c16 * 8);
        }
        CP_COMMIT();
    };

    float c[4][4][4];
    #pragma unroll
    for (int i = 0; i < 4; i++)
        #pragma unroll
        for (int j = 0; j < 4; j++)
            #pragma unroll
            for (int q = 0; q < 4; q++) c[i][j][q] = 0.f;

    const int a_row  = lane & 15;
    const int a_coff = (lane >> 4) << 3;
    const int b_row  = (lane & 7) + ((lane >> 4) << 3);
    const int b_coff = lane & 8;

    issue(0, 0);
    issue(1, 1);

    for (int kt = 0; kt < 32; kt++) {
        if (kt < 30) CP_WAIT1(); else CP_WAIT0();
        __syncthreads();
        if (kt + 2 < 32) issue(kt + 2, (kt + 2) % 3);

        const unsigned cA = sb + (unsigned)(kt % 3) * PSTG;
        const unsigned cB = cA + 10240;
        #pragma unroll
        for (int d = 0; d < 32; d += 16) {
            unsigned af[4][4];
            #pragma unroll
            for (int mi = 0; mi < 4; mi++)
                ldsm4(af[mi][0], af[mi][1], af[mi][2], af[mi][3],
                      cA + (unsigned)(((wm * 64 + mi * 16 + a_row) * GS + d + a_coff) * 2));
            #pragma unroll
            for (int np = 0; np < 2; np++) {
                unsigned b0, b1, b2, b3;
                ldsm4(b0, b1, b2, b3,
                      cB + (unsigned)(((wn * 32 + np * 16 + b_row) * GS + d + b_coff) * 2));
                #pragma unroll
                for (int mi = 0; mi < 4; mi++) {
                    mma16816(c[mi][np * 2],     af[mi][0], af[mi][1], af[mi][2], af[mi][3], b0, b1);
                    mma16816(c[mi][np * 2 + 1], af[mi][0], af[mi][1], af[mi][2], af[mi][3], b2, b3);
                }
            }
        }
        __syncthreads();
    }

    // epilogue
    const int g  = lane >> 2;
    const int q2 = (lane & 3) * 2;
    if (mode == 3) {
        const float alpha = *alphap;
        #pragma unroll
        for (int mi = 0; mi < 4; mi++)
            #pragma unroll
            for (int half = 0; half < 2; half++) {
                int m = bm + wm * 64 + mi * 16 + g + half * 8;
                #pragma unroll
                for (int ni = 0; ni < 4; ni++) {
                    int n = bn + wn * 32 + ni * 8 + q2;
                    float2 o;
                    o.x = xres[(size_t)m * DM + n]     + alpha * (c[mi][ni][half * 2 + 0] + bias[n]);
                    o.y = xres[(size_t)m * DM + n + 1] + alpha * (c[mi][ni][half * 2 + 1] + bias[n + 1]);
                    *(float2*)&outf[(size_t)m * DM + n] = o;
                }
            }
    } else {
        bf16* outp = (mode == 0) ? g_Qb : (mode == 1) ? g_Kb : g_Vb;
        #pragma unroll
        for (int mi = 0; mi < 4; mi++)
            #pragma unroll
            for (int half = 0; half < 2; half++) {
                int m = bm + wm * 64 + mi * 16 + g + half * 8;
                int b_ = m >> 11, t_ = m & 2047;
                #pragma unroll
                for (int ni = 0; ni < 4; ni++) {
                    int n = bn + wn * 32 + ni * 8 + q2;
                    int h = n >> 6, hd = n & 63;
                    size_t rb = ((size_t)(b_ * NH + h) * TT + t_);
                    float v0 = c[mi][ni][half * 2 + 0] + bias[n];
                    float v1 = c[mi][ni][half * 2 + 1] + bias[n + 1];
                    st2(&outp[rb * 64 + hd],
                        __float2bfloat16_rn(v0), __float2bfloat16_rn(v1));
                }
            }
    }
}

// ---------------- attention (HMMA): Q in regs, cp.async double-buffered K/V ----------------
// CTA = (b*H+h, 128-q tile); 8 warps, warp = 16 q-rows x full 128-key tile.
__global__ __launch_bounds__(256, 2) void attn_mma()
{
    extern __shared__ char smraw[];
    const int tid = threadIdx.x, lane = tid & 31, wid = tid >> 5;
    const int bh = blockIdx.x, qt = blockIdx.y;
    const bf16* Qg = g_Qb + (size_t)(bh * TT + qt * 128) * 64;
    const bf16* Kg = g_Kb + (size_t)bh * TT * 64;
    const bf16* Vg = g_Vb + (size_t)bh * TT * 64;

    unsigned sb = (unsigned)__cvta_generic_to_shared(smraw);

    // issue K/V tile t into stage s (1024 chunks each matrix, 4/thread)
    auto issueKV = [&](int t, int s) {
        const bf16* Kt = Kg + (size_t)t * 128 * 64;
        const bf16* Vt = Vg + (size_t)t * 128 * 64;
        const unsigned dK = sb + (unsigned)s * ASTG;
        const unsigned dV = dK + 18432;
        #pragma unroll
        for (int i = 0; i < 4; i++) {
            int e = tid + i * 256;
            int row = e >> 3, c16 = e & 7;
            cpa16(dK + row * 144 + c16 * 16, Kt + (size_t)row * 64 + c16 * 8);
            cpa16(dV + row * 144 + c16 * 16, Vt + (size_t)row * 64 + c16 * 8);
        }
        CP_COMMIT();
    };

    // stage0 K/V for tile 0, Q into stage1 K region
    issueKV(0, 0);
    {
        const unsigned dQ = sb + ASTG;
        #pragma unroll
        for (int i = 0; i < 4; i++) {
            int e = tid + i * 256;
            int row = e >> 3, c16 = e & 7;
            cpa16(dQ + row * 144 + c16 * 16, Qg + (size_t)row * 64 + c16 * 8);
        }
        CP_COMMIT();
    }

    const int a_row  = lane & 15;
    const int a_coff = (lane >> 4) << 3;
    const int b_row  = (lane & 7) + ((lane >> 4) << 3);
    const int b_coff = lane & 8;
    const int v_row  = (lane & 7) + (lane & 8);
    const int v_coff = (lane >> 4) << 3;
    const int qr = wid * 16;

    CP_WAIT0();
    __syncthreads();

    // hoist Q fragments to registers (frees stage1 for the pipeline)
    unsigned qf[4][4];
    #pragma unroll
    for (int d16 = 0; d16 < 4; d16++)
        ldsm4(qf[d16][0], qf[d16][1], qf[d16][2], qf[d16][3],
              sb + ASTG + (unsigned)(((qr + a_row) * 144) + (d16 * 16 + a_coff) * 2));
    __syncthreads();

    float oc[8][4];
    #pragma unroll
    for (int i = 0; i < 8; i++)
        #pragma unroll
        for (int j = 0; j < 4; j++) oc[i][j] = 0.f;
    float ds0 = 0.f, ds1 = 0.f;

    for (int kt = 0; kt < 16; kt++) {
        if (kt < 15) { issueKV(kt + 1, (kt + 1) & 1); CP_WAIT1(); }
        else CP_WAIT0();
        __syncthreads();

        const unsigned cK = sb + (unsigned)(kt & 1) * ASTG;
        const unsigned cV = cK + 18432;

        #pragma unroll
        for (int half = 0; half < 2; half++) {
            // S half: 16 q-rows x 64 keys
            float sc[8][4];
            #pragma unroll
            for (int i = 0; i < 8; i++)
                #pragma unroll
                for (int j = 0; j < 4; j++) sc[i][j] = 0.f;

            #pragma unroll
            for (int np = 0; np < 4; np++) {
                const int npg = half * 4 + np;
                #pragma unroll
                for (int d16 = 0; d16 < 4; d16++) {
                    unsigned b0, b1, b2, b3;
                    ldsm4(b0, b1, b2, b3,
                          cK + (unsigned)(((npg * 16 + b_row) * 144) + (d16 * 16 + b_coff) * 2));
                    mma16816(sc[np * 2],     qf[d16][0], qf[d16][1], qf[d16][2], qf[d16][3], b0, b1);
                    mma16816(sc[np * 2 + 1], qf[d16][0], qf[d16][1], qf[d16][2], qf[d16][3], b2, b3);
                }
            }

            // sigmoid gates + denominator partials
            #pragma unroll
            for (int nt = 0; nt < 8; nt++) {
                float g0 = sigm8(sc[nt][0]);
                float g1 = sigm8(sc[nt][1]);
                float g2 = sigm8(sc[nt][2]);
                float g3 = sigm8(sc[nt][3]);
                sc[nt][0] = g0; sc[nt][1] = g1; sc[nt][2] = g2; sc[nt][3] = g3;
                ds0 += g0 + g1;
                ds1 += g2 + g3;
            }

            // O += P_half . V_half
            #pragma unroll
            for (int t = 0; t < 4; t++) {
                const int tg = half * 4 + t;
                unsigned a0 = pack2(sc[2 * t][0],     sc[2 * t][1]);
                unsigned a1 = pack2(sc[2 * t][2],     sc[2 * t][3]);
                unsigned a2 = pack2(sc[2 * t + 1][0], sc[2 * t + 1][1]);
                unsigned a3 = pack2(sc[2 * t + 1][2], sc[2 * t + 1][3]);
                #pragma unroll
                for (int nq = 0; nq < 4; nq++) {
                    unsigned b0, b1, b2, b3;
                    ldsm4t(b0, b1, b2, b3,
                           cV + (unsigned)(((tg * 16 + v_row) * 144) + (nq * 16 + v_coff) * 2));
                    mma16816(oc[nq * 2],     a0, a1, a2, a3, b0, b1);
                    mma16816(oc[nq * 2 + 1], a0, a1, a2, a3, b2, b3);
                }
            }
        }
        __syncthreads();
    }

    // denominator reduce across the quad
    ds0 += __shfl_xor_sync(0xffffffffu, ds0, 1);
    ds0 += __shfl_xor_sync(0xffffffffu, ds0, 2);
    ds1 += __shfl_xor_sync(0xffffffffu, ds1, 1);
    ds1 += __shfl_xor_sync(0xffffffffu, ds1, 2);
    const float inv0 = 1.f / (ds0 + 1e-6f);
    const float inv1 = 1.f / (ds1 + 1e-6f);

    // epilogue: normalized O -> g_Ob [B,T,D] bf16
    const int b_ = bh >> 4, h = bh & 15;
    const int g = lane >> 2, q2 = (lane & 3) * 2;
    const int t0 = qt * 128 + qr + g;
    const size_t r0 = (size_t)(b_ * TT + t0) * DM + h * 64;
    const size_t r1 = r0 + (size_t)8 * DM;
    #pragma unroll
    for (int nt = 0; nt < 8; nt++) {
        int hd = nt * 8 + q2;
        st2(&g_Ob[r0 + hd], __float2bfloat16_rn(oc[nt][0] * inv0),
                            __float2bfloat16_rn(oc[nt][1] * inv0));
        st2(&g_Ob[r1 + hd], __float2bfloat16_rn(oc[nt][2] * inv1),
                            __float2bfloat16_rn(oc[nt][3] * inv1));
    }
}

// ---------------------------------------------------------------------------
extern "C" void kernel_launch(void* const* d_in, const int* in_sizes, int n_in,
                              void* d_out, int out_size)
{
    const float* x  = (const float*)d_in[0];
    const float* wq = (const float*)d_in[1];
    const float* bq = (const float*)d_in[2];
    const float* wk = (const float*)d_in[3];
    const float* bk = (const float*)d_in[4];
    const float* wv = (const float*)d_in[5];
    const float* bv = (const float*)d_in[6];
    const float* wo = (const float*)d_in[7];
    const float* bo = (const float*)d_in[8];
    const float* al = (const float*)d_in[9];
    float* out = (float*)d_out;

    cudaFuncSetAttribute(proj_mma, cudaFuncAttributeMaxDynamicSharedMemorySize, PSMEM);
    cudaFuncSetAttribute(attn_mma, cudaFuncAttributeMaxDynamicSharedMemorySize, ASMEM);

    cvt_all<<<8192, 256>>>(x, wq, wk, wv, wo);

    // fused Q/K/V projections (grid.z selects mode 0/1/2)
    proj_mma<<<dim3(DM / 128, MT / 128, 3), 256, PSMEM>>>(bq, bk, bv, 0,
                                                          nullptr, nullptr, nullptr);

    attn_mma<<<dim3(BB * NH, TT / 128), 256, ASMEM>>>();

    // output projection + residual
    proj_mma<<<dim3(DM / 128, MT / 128, 1), 256, PSMEM>>>(bo, bo, bo, 3,
                                                          x, al, out);
}

// round 11
// speedup vs baseline: 7.9798x; 1.0145x over previous
#include <cuda_runtime.h>
#include <cuda_bf16.h>
#include <math.h>

#define TT 2048
#define DM 1024
#define NH 16
#define HDI 64
#define BB 2
#define MT (BB*TT)     // 4096
#define GS 40          // proj smem stride (bf16): 80B/row -> conflict-free ldmatrix

// proj pipeline: 4 stages, each A(10240B)+B(10240B)
#define PSTG 20480
#define PSMEM (4*PSTG)
// attn pipeline: 3 stages, each K(18432B)+V(18432B); Q staged via stage2 K region
#define ASTG 36864
#define ASMEM (3*ASTG)

typedef __nv_bfloat16 bf16;
typedef __nv_bfloat162 bf162;

// ---------------- scratch (__device__ globals; no allocation) ----------------
__device__ bf16 g_Xb[MT*DM];              // x in bf16
__device__ bf16 g_Wb[4][DM*DM];           // weights bf16 (q,k,v,o)
__device__ bf16 g_Qb[BB*NH*TT*HDI];       // per-head [B,H,T,64]
__device__ bf16 g_Kb[BB*NH*TT*HDI];
__device__ bf16 g_Vb[BB*NH*TT*HDI];
__device__ bf16 g_Ob[MT*DM];              // attn out [B,T,D] bf16 (A of out-proj)

// ---------------- helpers ----------------
__device__ __forceinline__ unsigned pack2(float a, float b) {
    bf162 t = __floats2bfloat162_rn(a, b);
    return *reinterpret_cast<unsigned*>(&t);
}
__device__ __forceinline__ void st2(bf16* p, bf16 a, bf16 b) {
    bf162 t; t.x = a; t.y = b;
    *reinterpret_cast<bf162*>(p) = t;
}
__device__ __forceinline__ void mma16816(float* c,
    unsigned a0, unsigned a1, unsigned a2, unsigned a3, unsigned b0, unsigned b1) {
    asm volatile(
        "mma.sync.aligned.m16n8k16.row.col.f32.bf16.bf16.f32 "
        "{%0,%1,%2,%3},{%4,%5,%6,%7},{%8,%9},{%0,%1,%2,%3};\n"
        : "+f"(c[0]), "+f"(c[1]), "+f"(c[2]), "+f"(c[3])
        : "r"(a0), "r"(a1), "r"(a2), "r"(a3), "r"(b0), "r"(b1));
}
__device__ __forceinline__ void ldsm4(unsigned& r0, unsigned& r1, unsigned& r2, unsigned& r3, unsigned addr) {
    asm volatile("ldmatrix.sync.aligned.m8n8.x4.shared.b16 {%0,%1,%2,%3},[%4];\n"
        : "=r"(r0), "=r"(r1), "=r"(r2), "=r"(r3) : "r"(addr));
}
__device__ __forceinline__ void ldsm4t(unsigned& r0, unsigned& r1, unsigned& r2, unsigned& r3, unsigned addr) {
    asm volatile("ldmatrix.sync.aligned.m8n8.x4.trans.shared.b16 {%0,%1,%2,%3},[%4];\n"
        : "=r"(r0), "=r"(r1), "=r"(r2), "=r"(r3) : "r"(addr));
}
__device__ __forceinline__ void cpa16(unsigned dst, const void* src) {
    asm volatile("cp.async.cg.shared.global [%0], [%1], 16;" :: "r"(dst), "l"(src));
}
#define CP_COMMIT() asm volatile("cp.async.commit_group;")
#define CP_WAIT2()  asm volatile("cp.async.wait_group 2;")
#define CP_WAIT1()  asm volatile("cp.async.wait_group 1;")
#define CP_WAIT0()  asm volatile("cp.async.wait_group 0;")

// sigmoid(s/8) = 0.5*tanh(s/16)+0.5  (single MUFU via tanh.approx)
__device__ __forceinline__ float sigm8(float s) {
    float t;
    asm("tanh.approx.f32 %0, %1;" : "=f"(t) : "f"(s * 0.0625f));
    return fmaf(t, 0.5f, 0.5f);
}

// ---------------- fp32 -> bf16, all 5 tensors in one launch ----------------
__global__ void cvt_all(const float* __restrict__ x,
                        const float* __restrict__ wq, const float* __restrict__ wk,
                        const float* __restrict__ wv, const float* __restrict__ wo)
{
    int b = blockIdx.x;
    const float* src;
    bf16* dst;
    if (b < 4096) {
        src = x + (size_t)b * 1024;
        dst = g_Xb + (size_t)b * 1024;
    } else {
        int w = (b - 4096) >> 10, r = (b - 4096) & 1023;
        src = ((w == 0) ? wq : (w == 1) ? wk : (w == 2) ? wv : wo) + (size_t)r * 1024;
        dst = g_Wb[w] + (size_t)r * 1024;
    }
    size_t i = (size_t)threadIdx.x * 4;
    float4 v = *(const float4*)(src + i);
    *(bf162*)(dst + i)     = __floats2bfloat162_rn(v.x, v.y);
    *(bf162*)(dst + i + 2) = __floats2bfloat162_rn(v.z, v.w);
}

// ---------------- projection GEMM (HMMA, cp.async 4-stage, 1 barrier/iter) ----------------
// C[M=4096,N=1024] = A[M,1024] . W[N,1024]^T (+bias)
// grid.z + base_mode -> mode. 0/1/2: per-head Q/K/V; 3: out = x + alpha*(C+bias)
__global__ __launch_bounds__(256, 2) void proj_mma(
    const float* __restrict__ b0p, const float* __restrict__ b1p,
    const float* __restrict__ b2p, int base_mode,
    const float* __restrict__ xres, const float* __restrict__ alphap,
    float* __restrict__ outf)
{
    extern __shared__ char smraw[];
    const int tid  = threadIdx.x;
    const int lane = tid & 31, wid = tid >> 5;
    const int wm = wid >> 2, wn = wid & 3;       // 2 m-warps x 4 n-warps; warp 64x32
    const int mode = base_mode + blockIdx.z;
    const float* bias = (blockIdx.z == 0) ? b0p : (blockIdx.z == 1) ? b1p : b2p;
    const int bm = blockIdx.y * 128, bn = blockIdx.x * 128;

    const bf16* A = (mode == 3) ? g_Ob : g_Xb;
    const bf16* W = g_Wb[mode];
    const bf16* Ag = A + (size_t)bm * DM;
    const bf16* Wg = W + (size_t)bn * DM;

    unsigned sb = (unsigned)__cvta_generic_to_shared(smraw);

    // issue k-chunk kt into stage s
    auto issue = [&](int kt, int s) {
        const unsigned dA = sb + (unsigned)s * PSTG;
        const unsigned dB = dA + 10240;
        const int koff = kt * 32;
        #pragma unroll
        for (int i = 0; i < 2; i++) {
            int e = tid + i * 256;
            int row = e >> 2, c16 = e & 3;
            cpa16(dA + row * 80 + c16 * 16, Ag + (size_t)row * DM + koff + c16 * 8);
            cpa16(dB + row * 80 + c16 * 16, Wg + (size_t)row * DM + koff + c16 * 8);
        }
        CP_COMMIT();
    };

    float c[4][4][4];
    #pragma unroll
    for (int i = 0; i < 4; i++)
        #pragma unroll
        for (int j = 0; j < 4; j++)
            #pragma unroll
            for (int q = 0; q < 4; q++) c[i][j][q] = 0.f;

    const int a_row  = lane & 15;
    const int a_coff = (lane >> 4) << 3;
    const int b_row  = (lane & 7) + ((lane >> 4) << 3);
    const int b_coff = lane & 8;

    issue(0, 0);
    issue(1, 1);
    issue(2, 2);

    for (int kt = 0; kt < 32; kt++) {
        // ensure chunk kt has landed (up to 2 newer groups may stay in flight)
        if (kt < 30) CP_WAIT2();
        else if (kt == 30) CP_WAIT1();
        else CP_WAIT0();
        __syncthreads();   // all warps done reading stage (kt-1)&3; cp.async data visible
        if (kt + 3 < 32) issue(kt + 3, (kt + 3) & 3);

        const unsigned cA = sb + (unsigned)(kt & 3) * PSTG;
        const unsigned cB = cA + 10240;
        #pragma unroll
        for (int d = 0; d < 32; d += 16) {
            unsigned af[4][4];
            #pragma unroll
            for (int mi = 0; mi < 4; mi++)
                ldsm4(af[mi][0], af[mi][1], af[mi][2], af[mi][3],
                      cA + (unsigned)(((wm * 64 + mi * 16 + a_row) * GS + d + a_coff) * 2));
            #pragma unroll
            for (int np = 0; np < 2; np++) {
                unsigned b0, b1, b2, b3;
                ldsm4(b0, b1, b2, b3,
                      cB + (unsigned)(((wn * 32 + np * 16 + b_row) * GS + d + b_coff) * 2));
                #pragma unroll
                for (int mi = 0; mi < 4; mi++) {
                    mma16816(c[mi][np * 2],     af[mi][0], af[mi][1], af[mi][2], af[mi][3], b0, b1);
                    mma16816(c[mi][np * 2 + 1], af[mi][0], af[mi][1], af[mi][2], af[mi][3], b2, b3);
                }
            }
        }
        // no bottom barrier: next iteration's top barrier provides the ordering
    }

    // epilogue
    const int g  = lane >> 2;
    const int q2 = (lane & 3) * 2;
    if (mode == 3) {
        const float alpha = *alphap;
        #pragma unroll
        for (int mi = 0; mi < 4; mi++)
            #pragma unroll
            for (int half = 0; half < 2; half++) {
                int m = bm + wm * 64 + mi * 16 + g + half * 8;
                #pragma unroll
                for (int ni = 0; ni < 4; ni++) {
                    int n = bn + wn * 32 + ni * 8 + q2;
                    float2 o;
                    o.x = xres[(size_t)m * DM + n]     + alpha * (c[mi][ni][half * 2 + 0] + bias[n]);
                    o.y = xres[(size_t)m * DM + n + 1] + alpha * (c[mi][ni][half * 2 + 1] + bias[n + 1]);
                    *(float2*)&outf[(size_t)m * DM + n] = o;
                }
            }
    } else {
        bf16* outp = (mode == 0) ? g_Qb : (mode == 1) ? g_Kb : g_Vb;
        #pragma unroll
        for (int mi = 0; mi < 4; mi++)
            #pragma unroll
            for (int half = 0; half < 2; half++) {
                int m = bm + wm * 64 + mi * 16 + g + half * 8;
                int b_ = m >> 11, t_ = m & 2047;
                #pragma unroll
                for (int ni = 0; ni < 4; ni++) {
                    int n = bn + wn * 32 + ni * 8 + q2;
                    int h = n >> 6, hd = n & 63;
                    size_t rb = ((size_t)(b_ * NH + h) * TT + t_);
                    float v0 = c[mi][ni][half * 2 + 0] + bias[n];
                    float v1 = c[mi][ni][half * 2 + 1] + bias[n + 1];
                    st2(&outp[rb * 64 + hd],
                        __float2bfloat16_rn(v0), __float2bfloat16_rn(v1));
                }
            }
    }
}

// ---------------- attention (HMMA): Q in regs, cp.async 3-stage K/V, 1 barrier/iter ----------------
// CTA = (b*H+h, 128-q tile); 8 warps, warp = 16 q-rows x full 128-key tile.
__global__ __launch_bounds__(256, 2) void attn_mma()
{
    extern __shared__ char smraw[];
    const int tid = threadIdx.x, lane = tid & 31, wid = tid >> 5;
    const int bh = blockIdx.x, qt = blockIdx.y;
    const bf16* Qg = g_Qb + (size_t)(bh * TT + qt * 128) * 64;
    const bf16* Kg = g_Kb + (size_t)bh * TT * 64;
    const bf16* Vg = g_Vb + (size_t)bh * TT * 64;

    unsigned sb = (unsigned)__cvta_generic_to_shared(smraw);

    // issue K/V tile t into stage s
    auto issueKV = [&](int t, int s) {
        const bf16* Kt = Kg + (size_t)t * 128 * 64;
        const bf16* Vt = Vg + (size_t)t * 128 * 64;
        const unsigned dK = sb + (unsigned)s * ASTG;
        const unsigned dV = dK + 18432;
        #pragma unroll
        for (int i = 0; i < 4; i++) {
            int e = tid + i * 256;
            int row = e >> 3, c16 = e & 7;
            cpa16(dK + row * 144 + c16 * 16, Kt + (size_t)row * 64 + c16 * 8);
            cpa16(dV + row * 144 + c16 * 16, Vt + (size_t)row * 64 + c16 * 8);
        }
        CP_COMMIT();
    };

    // prologue: tiles 0,1 into stages 0,1; Q into stage2's K region
    issueKV(0, 0);
    issueKV(1, 1);
    {
        const unsigned dQ = sb + 2u * ASTG;
        #pragma unroll
        for (int i = 0; i < 4; i++) {
            int e = tid + i * 256;
            int row = e >> 3, c16 = e & 7;
            cpa16(dQ + row * 144 + c16 * 16, Qg + (size_t)row * 64 + c16 * 8);
        }
        CP_COMMIT();
    }

    const int a_row  = lane & 15;
    const int a_coff = (lane >> 4) << 3;
    const int b_row  = (lane & 7) + ((lane >> 4) << 3);
    const int b_coff = lane & 8;
    const int v_row  = (lane & 7) + (lane & 8);
    const int v_coff = (lane >> 4) << 3;
    const int qr = wid * 16;

    CP_WAIT0();
    __syncthreads();

    // hoist Q fragments to registers (stage2 K region gets recycled at kt=0)
    unsigned qf[4][4];
    #pragma unroll
    for (int d16 = 0; d16 < 4; d16++)
        ldsm4(qf[d16][0], qf[d16][1], qf[d16][2], qf[d16][3],
              sb + 2u * ASTG + (unsigned)(((qr + a_row) * 144) + (d16 * 16 + a_coff) * 2));

    float oc[8][4];
    #pragma unroll
    for (int i = 0; i < 8; i++)
        #pragma unroll
        for (int j = 0; j < 4; j++) oc[i][j] = 0.f;
    float ds0 = 0.f, ds1 = 0.f;

    for (int kt = 0; kt < 16; kt++) {
        // tile kt's group must be complete (newer may stay in flight)
        if (kt == 15) CP_WAIT0(); else CP_WAIT1();
        __syncthreads();   // orders Q-hoist/compute(kt-1) before stage reuse below
        if (kt + 2 < 16) issueKV(kt + 2, (kt + 2) % 3);

        const unsigned cK = sb + (unsigned)(kt % 3) * ASTG;
        const unsigned cV = cK + 18432;

        #pragma unroll
        for (int half = 0; half < 2; half++) {
            float sc[8][4];
            #pragma unroll
            for (int i = 0; i < 8; i++)
                #pragma unroll
                for (int j = 0; j < 4; j++) sc[i][j] = 0.f;

            #pragma unroll
            for (int np = 0; np < 4; np++) {
                const int npg = half * 4 + np;
                #pragma unroll
                for (int d16 = 0; d16 < 4; d16++) {
                    unsigned b0, b1, b2, b3;
                    ldsm4(b0, b1, b2, b3,
                          cK + (unsigned)(((npg * 16 + b_row) * 144) + (d16 * 16 + b_coff) * 2));
                    mma16816(sc[np * 2],     qf[d16][0], qf[d16][1], qf[d16][2], qf[d16][3], b0, b1);
                    mma16816(sc[np * 2 + 1], qf[d16][0], qf[d16][1], qf[d16][2], qf[d16][3], b2, b3);
                }
            }

            #pragma unroll
            for (int nt = 0; nt < 8; nt++) {
                float g0 = sigm8(sc[nt][0]);
                float g1 = sigm8(sc[nt][1]);
                float g2 = sigm8(sc[nt][2]);
                float g3 = sigm8(sc[nt][3]);
                sc[nt][0] = g0; sc[nt][1] = g1; sc[nt][2] = g2; sc[nt][3] = g3;
                ds0 += g0 + g1;
                ds1 += g2 + g3;
            }

            #pragma unroll
            for (int t = 0; t < 4; t++) {
                const int tg = half * 4 + t;
                unsigned a0 = pack2(sc[2 * t][0],     sc[2 * t][1]);
                unsigned a1 = pack2(sc[2 * t][2],     sc[2 * t][3]);
                unsigned a2 = pack2(sc[2 * t + 1][0], sc[2 * t + 1][1]);
                unsigned a3 = pack2(sc[2 * t + 1][2], sc[2 * t + 1][3]);
                #pragma unroll
                for (int nq = 0; nq < 4; nq++) {
                    unsigned b0, b1, b2, b3;
                    ldsm4t(b0, b1, b2, b3,
                           cV + (unsigned)(((tg * 16 + v_row) * 144) + (nq * 16 + v_coff) * 2));
                    mma16816(oc[nq * 2],     a0, a1, a2, a3, b0, b1);
                    mma16816(oc[nq * 2 + 1], a0, a1, a2, a3, b2, b3);
                }
            }
        }
        // no bottom barrier
    }

    // denominator reduce across the quad
    ds0 += __shfl_xor_sync(0xffffffffu, ds0, 1);
    ds0 += __shfl_xor_sync(0xffffffffu, ds0, 2);
    ds1 += __shfl_xor_sync(0xffffffffu, ds1, 1);
    ds1 += __shfl_xor_sync(0xffffffffu, ds1, 2);
    const float inv0 = 1.f / (ds0 + 1e-6f);
    const float inv1 = 1.f / (ds1 + 1e-6f);

    // epilogue: normalized O -> g_Ob [B,T,D] bf16
    const int b_ = bh >> 4, h = bh & 15;
    const int g = lane >> 2, q2 = (lane & 3) * 2;
    const int t0 = qt * 128 + qr + g;
    const size_t r0 = (size_t)(b_ * TT + t0) * DM + h * 64;
    const size_t r1 = r0 + (size_t)8 * DM;
    #pragma unroll
    for (int nt = 0; nt < 8; nt++) {
        int hd = nt * 8 + q2;
        st2(&g_Ob[r0 + hd], __float2bfloat16_rn(oc[nt][0] * inv0),
                            __float2bfloat16_rn(oc[nt][1] * inv0));
        st2(&g_Ob[r1 + hd], __float2bfloat16_rn(oc[nt][2] * inv1),
                            __float2bfloat16_rn(oc[nt][3] * inv1));
    }
}

// ---------------------------------------------------------------------------
extern "C" void kernel_launch(void* const* d_in, const int* in_sizes, int n_in,
                              void* d_out, int out_size)
{
    const float* x  = (const float*)d_in[0];
    const float* wq = (const float*)d_in[1];
    const float* bq = (const float*)d_in[2];
    const float* wk = (const float*)d_in[3];
    const float* bk = (const float*)d_in[4];
    const float* wv = (const float*)d_in[5];
    const float* bv = (const float*)d_in[6];
    const float* wo = (const float*)d_in[7];
    const float* bo = (const float*)d_in[8];
    const float* al = (const float*)d_in[9];
    float* out = (float*)d_out;

    cudaFuncSetAttribute(proj_mma, cudaFuncAttributeMaxDynamicSharedMemorySize, PSMEM);
    cudaFuncSetAttribute(attn_mma, cudaFuncAttributeMaxDynamicSharedMemorySize, ASMEM);

    cvt_all<<<8192, 256>>>(x, wq, wk, wv, wo);

    // fused Q/K/V projections (grid.z selects mode 0/1/2)
    proj_mma<<<dim3(DM / 128, MT / 128, 3), 256, PSMEM>>>(bq, bk, bv, 0,
                                                          nullptr, nullptr, nullptr);

    attn_mma<<<dim3(BB * NH, TT / 128), 256, ASMEM>>>();

    // output projection + residual
    proj_mma<<<dim3(DM / 128, MT / 128, 1), 256, PSMEM>>>(bo, bo, bo, 3,
                                                          x, al, out);
}